// round 12
// baseline (speedup 1.0000x reference)
#include <cuda_runtime.h>
#include <cuda_bf16.h>
#include <math.h>
#include <stdint.h>

#define CC 256
#define HH 56
#define WW 56
#define PP (HH*WW)        // 3136
#define BB 16
#define NTOT (BB*CC*PP)
#define EPSF 1e-5f
#define PADP 3840         // padded plane: 60 rows x 64 cols (bf16)
#define SPITCH 65         // k_dw smem pitch (floats) — conflict-free

// GEMM tiling: CTA 64(M) x 128(N), K-tile 64, 2-stage cp.async, 128 threads
#define KT 64
#define A_STAGE_BYTES (64*128)
#define B_STAGE_BYTES (64*256)
#define STAGE_BYTES (A_STAGE_BYTES + B_STAGE_BYTES)   // 24576
#define NSTAGE 2
#define GEMM_SMEM (NSTAGE*STAGE_BYTES)                // 49152

// Scratch
__device__ __align__(16) __nv_bfloat16 g_xh[NTOT];
__device__ __align__(16) __nv_bfloat16 g_pad[BB*CC*PADP];
__device__ __align__(16) __nv_bfloat16 g_toph[NTOT];
__device__ __align__(16) __nv_bfloat16 g_out2h[NTOT];
__device__ __align__(16) __nv_bfloat16 g_w1h[CC*CC];
__device__ __align__(16) __nv_bfloat16 g_w2h[CC*CC];
__device__ float g_sum[BB*CC];
__device__ float g_se[BB*CC];

// ---------------------------------------------------------------------------
__device__ __forceinline__ uint32_t s2u(const void* p) {
    uint32_t a;
    asm("{ .reg .u64 t; cvta.to.shared.u64 t, %1; cvt.u32.u64 %0, t; }"
        : "=r"(a) : "l"(p));
    return a;
}
__device__ __forceinline__ void cpa16(uint32_t dst, const void* src, bool pred) {
    asm volatile("cp.async.cg.shared.global [%0], [%1], 16, %2;"
                 :: "r"(dst), "l"(src), "r"(pred ? 16u : 0u));
}
#define CPA_COMMIT() asm volatile("cp.async.commit_group;" ::: "memory")

__device__ __forceinline__ void ldsm4(uint32_t& r0, uint32_t& r1, uint32_t& r2,
                                      uint32_t& r3, uint32_t addr) {
    asm volatile("ldmatrix.sync.aligned.m8n8.x4.shared.b16 {%0,%1,%2,%3}, [%4];"
                 : "=r"(r0), "=r"(r1), "=r"(r2), "=r"(r3) : "r"(addr));
}
__device__ __forceinline__ void ldsm4t(uint32_t& r0, uint32_t& r1, uint32_t& r2,
                                       uint32_t& r3, uint32_t addr) {
    asm volatile("ldmatrix.sync.aligned.m8n8.x4.trans.shared.b16 {%0,%1,%2,%3}, [%4];"
                 : "=r"(r0), "=r"(r1), "=r"(r2), "=r"(r3) : "r"(addr));
}
__device__ __forceinline__ void mma_bf16(float c[4], const uint32_t a[4],
                                         const uint32_t b[2]) {
    asm volatile(
        "mma.sync.aligned.m16n8k16.row.col.f32.bf16.bf16.f32 "
        "{%0,%1,%2,%3}, {%4,%5,%6,%7}, {%8,%9}, {%0,%1,%2,%3};"
        : "+f"(c[0]), "+f"(c[1]), "+f"(c[2]), "+f"(c[3])
        : "r"(a[0]), "r"(a[1]), "r"(a[2]), "r"(a[3]), "r"(b[0]), "r"(b[1]));
}

// packed f32x2 helpers (Blackwell FFMA2 — only reachable via PTX)
__device__ __forceinline__ uint64_t pack2(float lo, float hi) {
    uint64_t r;
    asm("mov.b64 %0, {%1, %2};" : "=l"(r) : "f"(lo), "f"(hi));
    return r;
}
__device__ __forceinline__ void unpack2(uint64_t p, float& lo, float& hi) {
    asm("mov.b64 {%0, %1}, %2;" : "=f"(lo), "=f"(hi) : "l"(p));
}
__device__ __forceinline__ uint64_t fma2(uint64_t a, uint64_t b, uint64_t c) {
    uint64_t d;
    asm("fma.rn.f32x2 %0, %1, %2, %3;" : "=l"(d) : "l"(a), "l"(b), "l"(c));
    return d;
}

// ---------------------------------------------------------------------------
// GEMM mainloop (R10 proven config): C[64 x 128] = A[64 x 256] * B[256 x 128]
__device__ __forceinline__ void gemm_main(const __nv_bfloat16* __restrict__ Ag,
                                          const __nv_bfloat16* __restrict__ Bg,
                                          int nvalid, float c[2][8][4]) {
    extern __shared__ char sm[];
    const int tid  = threadIdx.x;
    const int lane = tid & 31;
    const int w    = tid >> 5;
    const int wm   = w >> 1, wn = w & 1;
    const uint32_t sbase = s2u(sm);

    const int rowl = (lane & 7) + ((lane >> 3) & 1) * 8;
    const int hi   = lane >> 4;
    const int xr   = rowl & 7;

    #pragma unroll
    for (int i = 0; i < 2; i++)
        #pragma unroll
        for (int j = 0; j < 8; j++)
            #pragma unroll
            for (int r = 0; r < 4; r++) c[i][j][r] = 0.f;

    auto load_stage = [&](int t) {
        const int kt = t * KT;
        const uint32_t abase = sbase + (uint32_t)(t & 1) * STAGE_BYTES;
        const uint32_t bbase = abase + A_STAGE_BYTES;
        #pragma unroll
        for (int it = 0; it < 4; it++) {
            int q  = tid + it * 128;
            int m  = q >> 3, ch = q & 7;
            cpa16(abase + m*128 + ((ch ^ (m & 7)) << 4),
                  Ag + (size_t)m * 256 + kt + ch * 8, true);
        }
        #pragma unroll
        for (int it = 0; it < 8; it++) {
            int q  = tid + it * 128;
            int k  = q >> 4, ch = q & 15;
            cpa16(bbase + k*256 + ((ch ^ (k & 7)) << 4),
                  Bg + (size_t)(kt + k) * PP + ch * 8, ch * 8 < nvalid);
        }
        CPA_COMMIT();
    };

    load_stage(0); load_stage(1);

    const uint32_t a_off = (uint32_t)((wm*32 + rowl) * 128);
    const uint32_t b_off = (uint32_t)(A_STAGE_BYTES + rowl * 256);

    #pragma unroll 1
    for (int t = 0; t < 4; t++) {
        asm volatile("cp.async.wait_group 1;" ::: "memory");
        __syncthreads();

        const uint32_t st = sbase + (uint32_t)(t & 1) * STAGE_BYTES;
        #pragma unroll
        for (int kk2 = 0; kk2 < 4; kk2++) {
            uint32_t a[2][4], bf[8][2];
            #pragma unroll
            for (int i = 0; i < 2; i++)
                ldsm4(a[i][0], a[i][1], a[i][2], a[i][3],
                      st + a_off + i*16*128 + (((kk2*2 + hi) ^ xr) << 4));
            #pragma unroll
            for (int j2 = 0; j2 < 4; j2++)
                ldsm4t(bf[j2*2][0], bf[j2*2][1], bf[j2*2+1][0], bf[j2*2+1][1],
                       st + b_off + kk2*16*256 + (((wn*8 + j2*2 + hi) ^ xr) << 4));
            #pragma unroll
            for (int i = 0; i < 2; i++)
                #pragma unroll
                for (int j = 0; j < 8; j++)
                    mma_bf16(c[i][j], a[i], bf[j]);
        }
        __syncthreads();
        if (t + 2 < 4) load_stage(t + 2);
        else           CPA_COMMIT();
    }
}

// ---------------------------------------------------------------------------
// K1: pw1 GEMM -> g_pad (bf16, padded 60x64 planes)
__global__ __launch_bounds__(128, 4) void k_pw1() {
    const int b  = blockIdx.z;
    const int o0 = blockIdx.y * 64;
    const int p0 = blockIdx.x * 128;
    const int lane = threadIdx.x & 31, w = threadIdx.x >> 5;
    const int wm = w >> 1, wn = w & 1;

    float c[2][8][4];
    gemm_main(g_w1h + (size_t)o0 * 256, g_xh + (size_t)b * CC * PP + p0, PP - p0, c);

    __nv_bfloat16* dst = g_pad + (size_t)(b * CC) * PADP;
    #pragma unroll
    for (int i = 0; i < 2; i++) {
        int o = o0 + wm*32 + i*16 + (lane >> 2);
        #pragma unroll
        for (int j = 0; j < 8; j++) {
            int p = p0 + wn*64 + j*8 + (lane & 3)*2;
            if (p < PP) {
                int h = p / WW, ww = p - h * WW;
                int off = (h + 2) * 64 + ww + 2;
                *reinterpret_cast<__nv_bfloat162*>(dst + (size_t)o * PADP + off) =
                    __floats2bfloat162_rn(c[i][j][0], c[i][j][1]);
                *reinterpret_cast<__nv_bfloat162*>(dst + (size_t)(o+8) * PADP + off) =
                    __floats2bfloat162_rn(c[i][j][2], c[i][j][3]);
            }
        }
    }
}

// ---------------------------------------------------------------------------
// K3: pw2 GEMM + BN + ReLU + SE squeeze -> g_out2h (bf16), g_sum
__global__ __launch_bounds__(128, 4) void k_pw2(
    const float* __restrict__ bn2_g, const float* __restrict__ bn2_b,
    const float* __restrict__ bn2_m, const float* __restrict__ bn2_v) {
    const int b  = blockIdx.z;
    const int o0 = blockIdx.y * 64;
    const int p0 = blockIdx.x * 128;
    const int lane = threadIdx.x & 31, w = threadIdx.x >> 5;
    const int wm = w >> 1, wn = w & 1;

    float c[2][8][4];
    gemm_main(g_w2h + (size_t)o0 * 256, g_toph + (size_t)b * CC * PP + p0, PP - p0, c);

    __nv_bfloat16* dst = g_out2h + (size_t)b * CC * PP;
    #pragma unroll
    for (int i = 0; i < 2; i++) {
        int o = o0 + wm*32 + i*16 + (lane >> 2);
        float sc0 = bn2_g[o]   * rsqrtf(bn2_v[o]   + EPSF);
        float sh0 = bn2_b[o]   - bn2_m[o]   * sc0;
        float sc1 = bn2_g[o+8] * rsqrtf(bn2_v[o+8] + EPSF);
        float sh1 = bn2_b[o+8] - bn2_m[o+8] * sc1;
        float s0 = 0.f, s1 = 0.f;
        #pragma unroll
        for (int j = 0; j < 8; j++) {
            int pn = wn*64 + j*8 + (lane & 3)*2;
            if (p0 + pn < PP) {
                float v0 = fmaxf(fmaf(c[i][j][0], sc0, sh0), 0.f);
                float v1 = fmaxf(fmaf(c[i][j][1], sc0, sh0), 0.f);
                float v2 = fmaxf(fmaf(c[i][j][2], sc1, sh1), 0.f);
                float v3 = fmaxf(fmaf(c[i][j][3], sc1, sh1), 0.f);
                *reinterpret_cast<__nv_bfloat162*>(dst + (size_t)o * PP + p0 + pn) =
                    __floats2bfloat162_rn(v0, v1);
                *reinterpret_cast<__nv_bfloat162*>(dst + (size_t)(o+8) * PP + p0 + pn) =
                    __floats2bfloat162_rn(v2, v3);
                s0 += v0 + v1;
                s1 += v2 + v3;
            }
        }
        s0 += __shfl_xor_sync(0xFFFFFFFF, s0, 1);
        s0 += __shfl_xor_sync(0xFFFFFFFF, s0, 2);
        s1 += __shfl_xor_sync(0xFFFFFFFF, s1, 1);
        s1 += __shfl_xor_sync(0xFFFFFFFF, s1, 2);
        if ((lane & 3) == 0) {
            atomicAdd(&g_sum[b*CC + o],     s0);
            atomicAdd(&g_sum[b*CC + o + 8], s1);
        }
    }
}

// ---------------------------------------------------------------------------
// K0 (merged prep)
__global__ __launch_bounds__(256) void k_pre(const float* __restrict__ X,
                                             const float* __restrict__ W1,
                                             const float* __restrict__ W2) {
    const int bid = blockIdx.x;
    const int tid = threadIdx.x;

    size_t i = ((size_t)bid * 256 + tid) * 8;
    if (i < NTOT) {
        float4 a = *reinterpret_cast<const float4*>(X + i);
        float4 b = *reinterpret_cast<const float4*>(X + i + 4);
        __nv_bfloat162 o[4];
        o[0] = __floats2bfloat162_rn(a.x, a.y);
        o[1] = __floats2bfloat162_rn(a.z, a.w);
        o[2] = __floats2bfloat162_rn(b.x, b.y);
        o[3] = __floats2bfloat162_rn(b.z, b.w);
        *reinterpret_cast<uint4*>(g_xh + i) = *reinterpret_cast<uint4*>(o);
    }
    if (bid < 256) {
        int j = bid * 256 + tid;
        g_w1h[j] = __float2bfloat16(W1[j]);
        g_w2h[j] = __float2bfloat16(W2[j]);
    }
    if (bid < 16) g_sum[bid * 256 + tid] = 0.f;
    if (bid < BB*CC) {
        __nv_bfloat16* P = g_pad + (size_t)bid * PADP;
        {
            int r = tid >> 6;
            int row = (r < 2) ? r : 56 + r;
            P[row * 64 + (tid & 63)] = __nv_bfloat16(0.f);
        }
        #pragma unroll
        for (int it = 0; it < 2; it++) {
            int q = tid + it * 256;
            if (q < 448) {
                int row = 2 + (q >> 3);
                int ci = q & 7;
                int col = (ci < 2) ? ci : ci + 56;
                P[row * 64 + col] = __nv_bfloat16(0.f);
            }
        }
    }
}

// ---------------------------------------------------------------------------
// K2: fused depthwise + BN + ReLU + gate. Packed f32x2: each thread computes
// rows (r, r+28) in the two lanes. 28 row-pairs x 8 segments of 7 cols.
__global__ __launch_bounds__(256, 1) void k_dw(
    const float* __restrict__ xy3, const float* __restrict__ xy5,
    const float* __restrict__ bnxy_g, const float* __restrict__ bnxy_b,
    const float* __restrict__ bnxy_m, const float* __restrict__ bnxy_v,
    const float* __restrict__ xz3, const float* __restrict__ xz5,
    const float* __restrict__ bnxz_g, const float* __restrict__ bnxz_b,
    const float* __restrict__ bnxz_m, const float* __restrict__ bnxz_v,
    const float* __restrict__ yz3, const float* __restrict__ yz5,
    const float* __restrict__ bnyz_g, const float* __restrict__ bnyz_b,
    const float* __restrict__ bnyz_m, const float* __restrict__ bnyz_v,
    const float* __restrict__ alpha, const float* __restrict__ beta) {

    const int c = blockIdx.x;
    const int b = blockIdx.y;
    const int tid = threadIdx.x;

    __shared__ float sp[60*SPITCH];
    __shared__ float swe[36];

    {
        const __nv_bfloat16* src = g_pad + (size_t)(b*CC + c) * PADP;
        #pragma unroll
        for (int it = 0; it < 2; it++) {
            int idx = tid + it * 256;
            if (idx < 480) {
                int row = idx >> 3, col = (idx & 7) * 8;
                uint4 raw = *reinterpret_cast<const uint4*>(src + row*64 + col);
                const __nv_bfloat162* h2 = reinterpret_cast<const __nv_bfloat162*>(&raw);
                float* d = sp + row*SPITCH + col;
                #pragma unroll
                for (int q = 0; q < 4; q++) {
                    float2 f = __bfloat1622float2(h2[q]);
                    d[q*2]   = f.x;
                    d[q*2+1] = f.y;
                }
            }
        }
    }
    if (tid < 25) {
        int i = tid / 5, j = tid - i*5;
        float v = xy5[c*25 + tid];
        if (i >= 1 && i <= 3 && j >= 1 && j <= 3) v += xy3[c*9 + (i-1)*3 + (j-1)];
        swe[tid] = v;
    } else if (tid < 30) {
        int j = tid - 25;
        float v = xz5[c*5 + j];
        if (j >= 1 && j <= 3) v += xz3[c*3 + j - 1];
        swe[tid] = v;
    } else if (tid < 35) {
        int i = tid - 30;
        float v = yz5[c*5 + i];
        if (i >= 1 && i <= 3) v += yz3[c*3 + i - 1];
        swe[tid] = v;
    }
    __syncthreads();

    if (tid >= 224) return;
    const int pr  = tid >> 3;           // row pair 0..27 -> rows pr, pr+28
    const int seg = (tid & 7) * 7;      // 7-col segment

    const float scxy = bnxy_g[c] * rsqrtf(bnxy_v[c] + EPSF);
    const float shxy = bnxy_b[c] - bnxy_m[c] * scxy;
    const float scxz = bnxz_g[c] * rsqrtf(bnxz_v[c] + EPSF);
    const float shxz = bnxz_b[c] - bnxz_m[c] * scxz;
    const float scyz = bnyz_g[c] * rsqrtf(bnyz_v[c] + EPSF);
    const float shyz = bnyz_b[c] - bnyz_m[c] * scyz;
    const float al = alpha[c], be = beta[c];

    uint64_t wxy2[25], wxz2[5], wyz2[5];
    #pragma unroll
    for (int i = 0; i < 25; i++) wxy2[i] = pack2(swe[i], swe[i]);
    #pragma unroll
    for (int i = 0; i < 5; i++) { wxz2[i] = pack2(swe[25+i], swe[25+i]);
                                  wyz2[i] = pack2(swe[30+i], swe[30+i]); }

    const float* sprA = sp + pr*SPITCH + seg;
    const float* sprB = sp + (pr+28)*SPITCH + seg;

    uint64_t win[5][5];
    #pragma unroll
    for (int i = 0; i < 5; i++)
        #pragma unroll
        for (int j = 0; j < 5; j++)
            win[i][j] = pack2(sprA[i*SPITCH + j], sprB[i*SPITCH + j]);

    __nv_bfloat16* dstA = g_toph + (size_t)(b*CC + c) * PP + pr*WW + seg;
    __nv_bfloat16* dstB = dstA + 28*WW;

    #pragma unroll
    for (int s = 0; s < 7; s++) {
        uint64_t sxy = 0, sxz = 0, syz = 0;
        #pragma unroll
        for (int i = 0; i < 5; i++)
            #pragma unroll
            for (int j = 0; j < 5; j++)
                sxy = fma2(win[i][(s+j) % 5], wxy2[i*5+j], sxy);
        #pragma unroll
        for (int j = 0; j < 5; j++) sxz = fma2(win[2][(s+j) % 5], wxz2[j], sxz);
        #pragma unroll
        for (int i = 0; i < 5; i++) syz = fma2(win[i][(s+2) % 5], wyz2[i], syz);

        float xyA, xyB, xzA, xzB, yzA, yzB;
        unpack2(sxy, xyA, xyB);
        unpack2(sxz, xzA, xzB);
        unpack2(syz, yzA, yzB);

        float fxyA = fmaxf(fmaf(xyA, scxy, shxy), 0.f);
        float fxzA = fmaxf(fmaf(xzA, scxz, shxz), 0.f);
        float fyzA = fmaxf(fmaf(yzA, scyz, shyz), 0.f);
        float zA = fmaf(al, fxzA, be * fyzA);
        float gA = __fdividef(1.f, 1.f + __expf(-zA));
        dstA[s] = __float2bfloat16(fmaxf(fxyA * gA, 0.f));

        float fxyB = fmaxf(fmaf(xyB, scxy, shxy), 0.f);
        float fxzB = fmaxf(fmaf(xzB, scxz, shxz), 0.f);
        float fyzB = fmaxf(fmaf(yzB, scyz, shyz), 0.f);
        float zB = fmaf(al, fxzB, be * fyzB);
        float gB = __fdividef(1.f, 1.f + __expf(-zB));
        dstB[s] = __float2bfloat16(fmaxf(fxyB * gB, 0.f));

        if (s < 6) {
            #pragma unroll
            for (int i = 0; i < 5; i++)
                win[i][s % 5] = pack2(sprA[i*SPITCH + s + 5],
                                      sprB[i*SPITCH + s + 5]);
        }
    }
}

// ---------------------------------------------------------------------------
// K4: SE MLP per batch
__global__ __launch_bounds__(256) void k_se(
    const float* __restrict__ fc1_w, const float* __restrict__ fc1_b,
    const float* __restrict__ fc2_w, const float* __restrict__ fc2_b) {
    const int b = blockIdx.x;
    const int tid = threadIdx.x;
    __shared__ float s[CC];
    __shared__ float t[16];
    s[tid] = g_sum[b*CC + tid] * (1.f / (float)PP);
    __syncthreads();
    if (tid < 16) {
        float acc = fc1_b[tid];
        #pragma unroll 8
        for (int c = 0; c < CC; c++) acc = fmaf(fc1_w[tid*CC + c], s[c], acc);
        t[tid] = fmaxf(acc, 0.f);
    }
    __syncthreads();
    float acc = fc2_b[tid];
    #pragma unroll
    for (int m = 0; m < 16; m++) acc = fmaf(fc2_w[tid*16 + m], t[m], acc);
    g_se[b*CC + tid] = __fdividef(1.f, 1.f + __expf(-acc));
}

// ---------------------------------------------------------------------------
// K5: out = out2(bf16) * se[b,c] + x   (8 elems/thread)
__global__ __launch_bounds__(256) void k_final(const float* __restrict__ X,
                                               float* __restrict__ O) {
    size_t i = ((size_t)blockIdx.x * 256 + threadIdx.x) * 8;
    if (i >= NTOT) return;
    int bc = (int)(i / PP);
    float sf = g_se[bc];
    uint4 raw = *reinterpret_cast<const uint4*>(g_out2h + i);
    const __nv_bfloat162* h2 = reinterpret_cast<const __nv_bfloat162*>(&raw);
    float4 x0 = *reinterpret_cast<const float4*>(X + i);
    float4 x1 = *reinterpret_cast<const float4*>(X + i + 4);
    float2 f0 = __bfloat1622float2(h2[0]);
    float2 f1 = __bfloat1622float2(h2[1]);
    float2 f2 = __bfloat1622float2(h2[2]);
    float2 f3 = __bfloat1622float2(h2[3]);
    float4 r0, r1;
    r0.x = fmaf(f0.x, sf, x0.x); r0.y = fmaf(f0.y, sf, x0.y);
    r0.z = fmaf(f1.x, sf, x0.z); r0.w = fmaf(f1.y, sf, x0.w);
    r1.x = fmaf(f2.x, sf, x1.x); r1.y = fmaf(f2.y, sf, x1.y);
    r1.z = fmaf(f3.x, sf, x1.z); r1.w = fmaf(f3.y, sf, x1.w);
    *reinterpret_cast<float4*>(O + i)     = r0;
    *reinterpret_cast<float4*>(O + i + 4) = r1;
}

// ---------------------------------------------------------------------------
extern "C" void kernel_launch(void* const* d_in, const int* in_sizes, int n_in,
                              void* d_out, int out_size) {
    const float* x      = (const float*)d_in[0];
    const float* pw1_w  = (const float*)d_in[1];
    const float* xy3_w  = (const float*)d_in[2];
    const float* xy5_w  = (const float*)d_in[3];
    const float* bnxy_g = (const float*)d_in[4];
    const float* bnxy_b = (const float*)d_in[5];
    const float* bnxy_m = (const float*)d_in[6];
    const float* bnxy_v = (const float*)d_in[7];
    const float* xz3_w  = (const float*)d_in[8];
    const float* xz5_w  = (const float*)d_in[9];
    const float* bnxz_g = (const float*)d_in[10];
    const float* bnxz_b = (const float*)d_in[11];
    const float* bnxz_m = (const float*)d_in[12];
    const float* bnxz_v = (const float*)d_in[13];
    const float* yz3_w  = (const float*)d_in[14];
    const float* yz5_w  = (const float*)d_in[15];
    const float* bnyz_g = (const float*)d_in[16];
    const float* bnyz_b = (const float*)d_in[17];
    const float* bnyz_m = (const float*)d_in[18];
    const float* bnyz_v = (const float*)d_in[19];
    const float* alpha  = (const float*)d_in[20];
    const float* beta   = (const float*)d_in[21];
    const float* pw2_w  = (const float*)d_in[22];
    const float* bn2_g  = (const float*)d_in[23];
    const float* bn2_b  = (const float*)d_in[24];
    const float* bn2_m  = (const float*)d_in[25];
    const float* bn2_v  = (const float*)d_in[26];
    const float* fc1_w  = (const float*)d_in[27];
    const float* fc1_b  = (const float*)d_in[28];
    const float* fc2_w  = (const float*)d_in[29];
    const float* fc2_b  = (const float*)d_in[30];
    float* out = (float*)d_out;

    static bool attr_done = false;
    if (!attr_done) {
        cudaFuncSetAttribute(k_pw1, cudaFuncAttributeMaxDynamicSharedMemorySize, GEMM_SMEM);
        cudaFuncSetAttribute(k_pw2, cudaFuncAttributeMaxDynamicSharedMemorySize, GEMM_SMEM);
        attr_done = true;
    }

    k_pre<<<(NTOT/8 + 255)/256, 256>>>(x, pw1_w, pw2_w);
    k_pw1<<<dim3(25, 4, BB), 128, GEMM_SMEM>>>();
    k_dw<<<dim3(CC, BB), 256>>>(xy3_w, xy5_w, bnxy_g, bnxy_b, bnxy_m, bnxy_v,
                                xz3_w, xz5_w, bnxz_g, bnxz_b, bnxz_m, bnxz_v,
                                yz3_w, yz5_w, bnyz_g, bnyz_b, bnyz_m, bnyz_v,
                                alpha, beta);
    k_pw2<<<dim3(25, 4, BB), 128, GEMM_SMEM>>>(bn2_g, bn2_b, bn2_m, bn2_v);
    k_se<<<BB, 256>>>(fc1_w, fc1_b, fc2_w, fc2_b);
    k_final<<<(NTOT/8 + 255) / 256, 256>>>(x, out);
}

// round 13
// speedup vs baseline: 1.2103x; 1.2103x over previous
#include <cuda_runtime.h>
#include <cuda_bf16.h>
#include <math.h>
#include <stdint.h>

#define CC 256
#define HH 56
#define WW 56
#define PP (HH*WW)        // 3136
#define BB 16
#define NTOT (BB*CC*PP)
#define EPSF 1e-5f
#define PADP 3840         // padded plane: 60 rows x 64 cols (bf16)
#define SPITCH 65         // k_dw smem pitch (floats) — conflict-free

// GEMM tiling: CTA 64(M) x 128(N), K-tile 64, 2-stage cp.async, 128 threads
#define KT 64
#define A_STAGE_BYTES (64*128)
#define B_STAGE_BYTES (64*256)
#define STAGE_BYTES (A_STAGE_BYTES + B_STAGE_BYTES)   // 24576
#define NSTAGE 2
#define GEMM_SMEM (NSTAGE*STAGE_BYTES)                // 49152

// Scratch
__device__ __align__(16) __nv_bfloat16 g_xh[NTOT];
__device__ __align__(16) __nv_bfloat16 g_pad[BB*CC*PADP];
__device__ __align__(16) __nv_bfloat16 g_toph[NTOT];
__device__ __align__(16) __nv_bfloat16 g_out2h[NTOT];
__device__ __align__(16) __nv_bfloat16 g_w1h[CC*CC];
__device__ __align__(16) __nv_bfloat16 g_w2h[CC*CC];
__device__ float g_sum[BB*CC];
__device__ float g_se[BB*CC];

// ---------------------------------------------------------------------------
__device__ __forceinline__ uint32_t s2u(const void* p) {
    uint32_t a;
    asm("{ .reg .u64 t; cvta.to.shared.u64 t, %1; cvt.u32.u64 %0, t; }"
        : "=r"(a) : "l"(p));
    return a;
}
__device__ __forceinline__ void cpa16(uint32_t dst, const void* src, bool pred) {
    asm volatile("cp.async.cg.shared.global [%0], [%1], 16, %2;"
                 :: "r"(dst), "l"(src), "r"(pred ? 16u : 0u));
}
#define CPA_COMMIT() asm volatile("cp.async.commit_group;" ::: "memory")

__device__ __forceinline__ void ldsm4(uint32_t& r0, uint32_t& r1, uint32_t& r2,
                                      uint32_t& r3, uint32_t addr) {
    asm volatile("ldmatrix.sync.aligned.m8n8.x4.shared.b16 {%0,%1,%2,%3}, [%4];"
                 : "=r"(r0), "=r"(r1), "=r"(r2), "=r"(r3) : "r"(addr));
}
__device__ __forceinline__ void ldsm4t(uint32_t& r0, uint32_t& r1, uint32_t& r2,
                                       uint32_t& r3, uint32_t addr) {
    asm volatile("ldmatrix.sync.aligned.m8n8.x4.trans.shared.b16 {%0,%1,%2,%3}, [%4];"
                 : "=r"(r0), "=r"(r1), "=r"(r2), "=r"(r3) : "r"(addr));
}
__device__ __forceinline__ void mma_bf16(float c[4], const uint32_t a[4],
                                         const uint32_t b[2]) {
    asm volatile(
        "mma.sync.aligned.m16n8k16.row.col.f32.bf16.bf16.f32 "
        "{%0,%1,%2,%3}, {%4,%5,%6,%7}, {%8,%9}, {%0,%1,%2,%3};"
        : "+f"(c[0]), "+f"(c[1]), "+f"(c[2]), "+f"(c[3])
        : "r"(a[0]), "r"(a[1]), "r"(a[2]), "r"(a[3]), "r"(b[0]), "r"(b[1]));
}

// ---------------------------------------------------------------------------
// GEMM mainloop (R10 proven config): C[64 x 128] = A[64 x 256] * B[256 x 128]
__device__ __forceinline__ void gemm_main(const __nv_bfloat16* __restrict__ Ag,
                                          const __nv_bfloat16* __restrict__ Bg,
                                          int nvalid, float c[2][8][4]) {
    extern __shared__ char sm[];
    const int tid  = threadIdx.x;
    const int lane = tid & 31;
    const int w    = tid >> 5;
    const int wm   = w >> 1, wn = w & 1;
    const uint32_t sbase = s2u(sm);

    const int rowl = (lane & 7) + ((lane >> 3) & 1) * 8;
    const int hi   = lane >> 4;
    const int xr   = rowl & 7;

    #pragma unroll
    for (int i = 0; i < 2; i++)
        #pragma unroll
        for (int j = 0; j < 8; j++)
            #pragma unroll
            for (int r = 0; r < 4; r++) c[i][j][r] = 0.f;

    auto load_stage = [&](int t) {
        const int kt = t * KT;
        const uint32_t abase = sbase + (uint32_t)(t & 1) * STAGE_BYTES;
        const uint32_t bbase = abase + A_STAGE_BYTES;
        #pragma unroll
        for (int it = 0; it < 4; it++) {
            int q  = tid + it * 128;
            int m  = q >> 3, ch = q & 7;
            cpa16(abase + m*128 + ((ch ^ (m & 7)) << 4),
                  Ag + (size_t)m * 256 + kt + ch * 8, true);
        }
        #pragma unroll
        for (int it = 0; it < 8; it++) {
            int q  = tid + it * 128;
            int k  = q >> 4, ch = q & 15;
            cpa16(bbase + k*256 + ((ch ^ (k & 7)) << 4),
                  Bg + (size_t)(kt + k) * PP + ch * 8, ch * 8 < nvalid);
        }
        CPA_COMMIT();
    };

    load_stage(0); load_stage(1);

    const uint32_t a_off = (uint32_t)((wm*32 + rowl) * 128);
    const uint32_t b_off = (uint32_t)(A_STAGE_BYTES + rowl * 256);

    #pragma unroll 1
    for (int t = 0; t < 4; t++) {
        asm volatile("cp.async.wait_group 1;" ::: "memory");
        __syncthreads();

        const uint32_t st = sbase + (uint32_t)(t & 1) * STAGE_BYTES;
        #pragma unroll
        for (int kk2 = 0; kk2 < 4; kk2++) {
            uint32_t a[2][4], bf[8][2];
            #pragma unroll
            for (int i = 0; i < 2; i++)
                ldsm4(a[i][0], a[i][1], a[i][2], a[i][3],
                      st + a_off + i*16*128 + (((kk2*2 + hi) ^ xr) << 4));
            #pragma unroll
            for (int j2 = 0; j2 < 4; j2++)
                ldsm4t(bf[j2*2][0], bf[j2*2][1], bf[j2*2+1][0], bf[j2*2+1][1],
                       st + b_off + kk2*16*256 + (((wn*8 + j2*2 + hi) ^ xr) << 4));
            #pragma unroll
            for (int i = 0; i < 2; i++)
                #pragma unroll
                for (int j = 0; j < 8; j++)
                    mma_bf16(c[i][j], a[i], bf[j]);
        }
        __syncthreads();
        if (t + 2 < 4) load_stage(t + 2);
        else           CPA_COMMIT();
    }
}

// ---------------------------------------------------------------------------
// K1: pw1 GEMM -> g_pad (bf16, padded 60x64 planes)
__global__ __launch_bounds__(128, 4) void k_pw1() {
    const int b  = blockIdx.z;
    const int o0 = blockIdx.y * 64;
    const int p0 = blockIdx.x * 128;
    const int lane = threadIdx.x & 31, w = threadIdx.x >> 5;
    const int wm = w >> 1, wn = w & 1;

    float c[2][8][4];
    gemm_main(g_w1h + (size_t)o0 * 256, g_xh + (size_t)b * CC * PP + p0, PP - p0, c);

    __nv_bfloat16* dst = g_pad + (size_t)(b * CC) * PADP;
    #pragma unroll
    for (int i = 0; i < 2; i++) {
        int o = o0 + wm*32 + i*16 + (lane >> 2);
        #pragma unroll
        for (int j = 0; j < 8; j++) {
            int p = p0 + wn*64 + j*8 + (lane & 3)*2;
            if (p < PP) {
                int h = p / WW, ww = p - h * WW;
                int off = (h + 2) * 64 + ww + 2;
                *reinterpret_cast<__nv_bfloat162*>(dst + (size_t)o * PADP + off) =
                    __floats2bfloat162_rn(c[i][j][0], c[i][j][1]);
                *reinterpret_cast<__nv_bfloat162*>(dst + (size_t)(o+8) * PADP + off) =
                    __floats2bfloat162_rn(c[i][j][2], c[i][j][3]);
            }
        }
    }
}

// ---------------------------------------------------------------------------
// K3: pw2 GEMM + BN + ReLU + SE squeeze -> g_out2h (bf16), g_sum
__global__ __launch_bounds__(128, 4) void k_pw2(
    const float* __restrict__ bn2_g, const float* __restrict__ bn2_b,
    const float* __restrict__ bn2_m, const float* __restrict__ bn2_v) {
    const int b  = blockIdx.z;
    const int o0 = blockIdx.y * 64;
    const int p0 = blockIdx.x * 128;
    const int lane = threadIdx.x & 31, w = threadIdx.x >> 5;
    const int wm = w >> 1, wn = w & 1;

    float c[2][8][4];
    gemm_main(g_w2h + (size_t)o0 * 256, g_toph + (size_t)b * CC * PP + p0, PP - p0, c);

    __nv_bfloat16* dst = g_out2h + (size_t)b * CC * PP;
    #pragma unroll
    for (int i = 0; i < 2; i++) {
        int o = o0 + wm*32 + i*16 + (lane >> 2);
        float sc0 = bn2_g[o]   * rsqrtf(bn2_v[o]   + EPSF);
        float sh0 = bn2_b[o]   - bn2_m[o]   * sc0;
        float sc1 = bn2_g[o+8] * rsqrtf(bn2_v[o+8] + EPSF);
        float sh1 = bn2_b[o+8] - bn2_m[o+8] * sc1;
        float s0 = 0.f, s1 = 0.f;
        #pragma unroll
        for (int j = 0; j < 8; j++) {
            int pn = wn*64 + j*8 + (lane & 3)*2;
            if (p0 + pn < PP) {
                float v0 = fmaxf(fmaf(c[i][j][0], sc0, sh0), 0.f);
                float v1 = fmaxf(fmaf(c[i][j][1], sc0, sh0), 0.f);
                float v2 = fmaxf(fmaf(c[i][j][2], sc1, sh1), 0.f);
                float v3 = fmaxf(fmaf(c[i][j][3], sc1, sh1), 0.f);
                *reinterpret_cast<__nv_bfloat162*>(dst + (size_t)o * PP + p0 + pn) =
                    __floats2bfloat162_rn(v0, v1);
                *reinterpret_cast<__nv_bfloat162*>(dst + (size_t)(o+8) * PP + p0 + pn) =
                    __floats2bfloat162_rn(v2, v3);
                s0 += v0 + v1;
                s1 += v2 + v3;
            }
        }
        s0 += __shfl_xor_sync(0xFFFFFFFF, s0, 1);
        s0 += __shfl_xor_sync(0xFFFFFFFF, s0, 2);
        s1 += __shfl_xor_sync(0xFFFFFFFF, s1, 1);
        s1 += __shfl_xor_sync(0xFFFFFFFF, s1, 2);
        if ((lane & 3) == 0) {
            atomicAdd(&g_sum[b*CC + o],     s0);
            atomicAdd(&g_sum[b*CC + o + 8], s1);
        }
    }
}

// ---------------------------------------------------------------------------
// K0 (merged prep)
__global__ __launch_bounds__(256) void k_pre(const float* __restrict__ X,
                                             const float* __restrict__ W1,
                                             const float* __restrict__ W2) {
    const int bid = blockIdx.x;
    const int tid = threadIdx.x;

    size_t i = ((size_t)bid * 256 + tid) * 8;
    if (i < NTOT) {
        float4 a = *reinterpret_cast<const float4*>(X + i);
        float4 b = *reinterpret_cast<const float4*>(X + i + 4);
        __nv_bfloat162 o[4];
        o[0] = __floats2bfloat162_rn(a.x, a.y);
        o[1] = __floats2bfloat162_rn(a.z, a.w);
        o[2] = __floats2bfloat162_rn(b.x, b.y);
        o[3] = __floats2bfloat162_rn(b.z, b.w);
        *reinterpret_cast<uint4*>(g_xh + i) = *reinterpret_cast<uint4*>(o);
    }
    if (bid < 256) {
        int j = bid * 256 + tid;
        g_w1h[j] = __float2bfloat16(W1[j]);
        g_w2h[j] = __float2bfloat16(W2[j]);
    }
    if (bid < 16) g_sum[bid * 256 + tid] = 0.f;
    if (bid < BB*CC) {
        __nv_bfloat16* P = g_pad + (size_t)bid * PADP;
        {
            int r = tid >> 6;
            int row = (r < 2) ? r : 56 + r;
            P[row * 64 + (tid & 63)] = __nv_bfloat16(0.f);
        }
        #pragma unroll
        for (int it = 0; it < 2; it++) {
            int q = tid + it * 256;
            if (q < 448) {
                int row = 2 + (q >> 3);
                int ci = q & 7;
                int col = (ci < 2) ? ci : ci + 56;
                P[row * 64 + col] = __nv_bfloat16(0.f);
            }
        }
    }
}

// ---------------------------------------------------------------------------
// K2: fused depthwise + BN + ReLU + gate. Padded input, pitch-65 smem (scalar).
__global__ __launch_bounds__(256) void k_dw(
    const float* __restrict__ xy3, const float* __restrict__ xy5,
    const float* __restrict__ bnxy_g, const float* __restrict__ bnxy_b,
    const float* __restrict__ bnxy_m, const float* __restrict__ bnxy_v,
    const float* __restrict__ xz3, const float* __restrict__ xz5,
    const float* __restrict__ bnxz_g, const float* __restrict__ bnxz_b,
    const float* __restrict__ bnxz_m, const float* __restrict__ bnxz_v,
    const float* __restrict__ yz3, const float* __restrict__ yz5,
    const float* __restrict__ bnyz_g, const float* __restrict__ bnyz_b,
    const float* __restrict__ bnyz_m, const float* __restrict__ bnyz_v,
    const float* __restrict__ alpha, const float* __restrict__ beta) {

    const int c = blockIdx.x;
    const int b = blockIdx.y;
    const int tid = threadIdx.x;

    __shared__ float sp[60*SPITCH];
    __shared__ float swe[36];

    {
        const __nv_bfloat16* src = g_pad + (size_t)(b*CC + c) * PADP;
        #pragma unroll
        for (int it = 0; it < 2; it++) {
            int idx = tid + it * 256;
            if (idx < 480) {
                int row = idx >> 3, col = (idx & 7) * 8;
                uint4 raw = *reinterpret_cast<const uint4*>(src + row*64 + col);
                const __nv_bfloat162* h2 = reinterpret_cast<const __nv_bfloat162*>(&raw);
                float* d = sp + row*SPITCH + col;
                #pragma unroll
                for (int q = 0; q < 4; q++) {
                    float2 f = __bfloat1622float2(h2[q]);
                    d[q*2]   = f.x;
                    d[q*2+1] = f.y;
                }
            }
        }
    }
    if (tid < 25) {
        int i = tid / 5, j = tid - i*5;
        float v = xy5[c*25 + tid];
        if (i >= 1 && i <= 3 && j >= 1 && j <= 3) v += xy3[c*9 + (i-1)*3 + (j-1)];
        swe[tid] = v;
    } else if (tid < 30) {
        int j = tid - 25;
        float v = xz5[c*5 + j];
        if (j >= 1 && j <= 3) v += xz3[c*3 + j - 1];
        swe[tid] = v;
    } else if (tid < 35) {
        int i = tid - 30;
        float v = yz5[c*5 + i];
        if (i >= 1 && i <= 3) v += yz3[c*3 + i - 1];
        swe[tid] = v;
    }
    __syncthreads();

    if (tid >= 224) return;
    const int row = tid >> 2;
    const int seg = (tid & 3) * 14;

    const float scxy = bnxy_g[c] * rsqrtf(bnxy_v[c] + EPSF);
    const float shxy = bnxy_b[c] - bnxy_m[c] * scxy;
    const float scxz = bnxz_g[c] * rsqrtf(bnxz_v[c] + EPSF);
    const float shxz = bnxz_b[c] - bnxz_m[c] * scxz;
    const float scyz = bnyz_g[c] * rsqrtf(bnyz_v[c] + EPSF);
    const float shyz = bnyz_b[c] - bnyz_m[c] * scyz;
    const float al = alpha[c], be = beta[c];

    float we[25], wxz[5], wyz[5];
    #pragma unroll
    for (int i = 0; i < 25; i++) we[i] = swe[i];
    #pragma unroll
    for (int i = 0; i < 5; i++) { wxz[i] = swe[25+i]; wyz[i] = swe[30+i]; }

    float win[5][5];
    const float* spr = sp + row*SPITCH + seg;
    #pragma unroll
    for (int i = 0; i < 5; i++)
        #pragma unroll
        for (int j = 0; j < 5; j++)
            win[i][j] = spr[i*SPITCH + j];

    __nv_bfloat162 outbuf[7];
    #pragma unroll
    for (int s = 0; s < 14; s++) {
        float sxy = 0.f, sxz = 0.f, syz = 0.f;
        #pragma unroll
        for (int i = 0; i < 5; i++)
            #pragma unroll
            for (int j = 0; j < 5; j++)
                sxy = fmaf(win[i][(s+j) % 5], we[i*5+j], sxy);
        #pragma unroll
        for (int j = 0; j < 5; j++) sxz = fmaf(win[2][(s+j) % 5], wxz[j], sxz);
        #pragma unroll
        for (int i = 0; i < 5; i++) syz = fmaf(win[i][(s+2) % 5], wyz[i], syz);

        float fxy = fmaxf(fmaf(sxy, scxy, shxy), 0.f);
        float fxz = fmaxf(fmaf(sxz, scxz, shxz), 0.f);
        float fyz = fmaxf(fmaf(syz, scyz, shyz), 0.f);
        float z = fmaf(al, fxz, be * fyz);
        float gate = __fdividef(1.f, 1.f + __expf(-z));
        float r = fmaxf(fxy * gate, 0.f);
        __nv_bfloat16 h = __float2bfloat16(r);
        if (s & 1) outbuf[s >> 1].y = h;
        else       outbuf[s >> 1].x = h;

        if (s < 13) {
            #pragma unroll
            for (int i = 0; i < 5; i++)
                win[i][s % 5] = spr[i*SPITCH + s + 5];
        }
    }
    __nv_bfloat16* dst = g_toph + (size_t)(b*CC + c) * PP + row*WW + seg;
    #pragma unroll
    for (int s = 0; s < 7; s++)
        *reinterpret_cast<__nv_bfloat162*>(dst + 2*s) = outbuf[s];
}

// ---------------------------------------------------------------------------
// K4: SE MLP per batch
__global__ __launch_bounds__(256) void k_se(
    const float* __restrict__ fc1_w, const float* __restrict__ fc1_b,
    const float* __restrict__ fc2_w, const float* __restrict__ fc2_b) {
    const int b = blockIdx.x;
    const int tid = threadIdx.x;
    __shared__ float s[CC];
    __shared__ float t[16];
    s[tid] = g_sum[b*CC + tid] * (1.f / (float)PP);
    __syncthreads();
    if (tid < 16) {
        float acc = fc1_b[tid];
        #pragma unroll 8
        for (int c = 0; c < CC; c++) acc = fmaf(fc1_w[tid*CC + c], s[c], acc);
        t[tid] = fmaxf(acc, 0.f);
    }
    __syncthreads();
    float acc = fc2_b[tid];
    #pragma unroll
    for (int m = 0; m < 16; m++) acc = fmaf(fc2_w[tid*16 + m], t[m], acc);
    g_se[b*CC + tid] = __fdividef(1.f, 1.f + __expf(-acc));
}

// ---------------------------------------------------------------------------
// K5: out = out2(bf16) * se[b,c] + x   (8 elems/thread)
__global__ __launch_bounds__(256) void k_final(const float* __restrict__ X,
                                               float* __restrict__ O) {
    size_t i = ((size_t)blockIdx.x * 256 + threadIdx.x) * 8;
    if (i >= NTOT) return;
    int bc = (int)(i / PP);
    float sf = g_se[bc];
    uint4 raw = *reinterpret_cast<const uint4*>(g_out2h + i);
    const __nv_bfloat162* h2 = reinterpret_cast<const __nv_bfloat162*>(&raw);
    float4 x0 = *reinterpret_cast<const float4*>(X + i);
    float4 x1 = *reinterpret_cast<const float4*>(X + i + 4);
    float2 f0 = __bfloat1622float2(h2[0]);
    float2 f1 = __bfloat1622float2(h2[1]);
    float2 f2 = __bfloat1622float2(h2[2]);
    float2 f3 = __bfloat1622float2(h2[3]);
    float4 r0, r1;
    r0.x = fmaf(f0.x, sf, x0.x); r0.y = fmaf(f0.y, sf, x0.y);
    r0.z = fmaf(f1.x, sf, x0.z); r0.w = fmaf(f1.y, sf, x0.w);
    r1.x = fmaf(f2.x, sf, x1.x); r1.y = fmaf(f2.y, sf, x1.y);
    r1.z = fmaf(f3.x, sf, x1.z); r1.w = fmaf(f3.y, sf, x1.w);
    *reinterpret_cast<float4*>(O + i)     = r0;
    *reinterpret_cast<float4*>(O + i + 4) = r1;
}

// ---------------------------------------------------------------------------
extern "C" void kernel_launch(void* const* d_in, const int* in_sizes, int n_in,
                              void* d_out, int out_size) {
    const float* x      = (const float*)d_in[0];
    const float* pw1_w  = (const float*)d_in[1];
    const float* xy3_w  = (const float*)d_in[2];
    const float* xy5_w  = (const float*)d_in[3];
    const float* bnxy_g = (const float*)d_in[4];
    const float* bnxy_b = (const float*)d_in[5];
    const float* bnxy_m = (const float*)d_in[6];
    const float* bnxy_v = (const float*)d_in[7];
    const float* xz3_w  = (const float*)d_in[8];
    const float* xz5_w  = (const float*)d_in[9];
    const float* bnxz_g = (const float*)d_in[10];
    const float* bnxz_b = (const float*)d_in[11];
    const float* bnxz_m = (const float*)d_in[12];
    const float* bnxz_v = (const float*)d_in[13];
    const float* yz3_w  = (const float*)d_in[14];
    const float* yz5_w  = (const float*)d_in[15];
    const float* bnyz_g = (const float*)d_in[16];
    const float* bnyz_b = (const float*)d_in[17];
    const float* bnyz_m = (const float*)d_in[18];
    const float* bnyz_v = (const float*)d_in[19];
    const float* alpha  = (const float*)d_in[20];
    const float* beta   = (const float*)d_in[21];
    const float* pw2_w  = (const float*)d_in[22];
    const float* bn2_g  = (const float*)d_in[23];
    const float* bn2_b  = (const float*)d_in[24];
    const float* bn2_m  = (const float*)d_in[25];
    const float* bn2_v  = (const float*)d_in[26];
    const float* fc1_w  = (const float*)d_in[27];
    const float* fc1_b  = (const float*)d_in[28];
    const float* fc2_w  = (const float*)d_in[29];
    const float* fc2_b  = (const float*)d_in[30];
    float* out = (float*)d_out;

    static bool attr_done = false;
    if (!attr_done) {
        cudaFuncSetAttribute(k_pw1, cudaFuncAttributeMaxDynamicSharedMemorySize, GEMM_SMEM);
        cudaFuncSetAttribute(k_pw2, cudaFuncAttributeMaxDynamicSharedMemorySize, GEMM_SMEM);
        attr_done = true;
    }

    k_pre<<<(NTOT/8 + 255)/256, 256>>>(x, pw1_w, pw2_w);
    k_pw1<<<dim3(25, 4, BB), 128, GEMM_SMEM>>>();
    k_dw<<<dim3(CC, BB), 256>>>(xy3_w, xy5_w, bnxy_g, bnxy_b, bnxy_m, bnxy_v,
                                xz3_w, xz5_w, bnxz_g, bnxz_b, bnxz_m, bnxz_v,
                                yz3_w, yz5_w, bnyz_g, bnyz_b, bnyz_m, bnyz_v,
                                alpha, beta);
    k_pw2<<<dim3(25, 4, BB), 128, GEMM_SMEM>>>(bn2_g, bn2_b, bn2_m, bn2_v);
    k_se<<<BB, 256>>>(fc1_w, fc1_b, fc2_w, fc2_b);
    k_final<<<(NTOT/8 + 255) / 256, 256>>>(x, out);
}

// round 17
// speedup vs baseline: 1.2208x; 1.0087x over previous
#include <cuda_runtime.h>
#include <cuda_bf16.h>
#include <math.h>
#include <stdint.h>

#define CC 256
#define HH 56
#define WW 56
#define PP (HH*WW)        // 3136
#define BB 16
#define NTOT (BB*CC*PP)
#define EPSF 1e-5f
#define PADP 3840         // padded plane: 60 rows x 64 cols (bf16)
#define SPITCH 65         // k_dw smem pitch (floats) — conflict-free

// GEMM tiling: CTA 64(M) x 128(N), K-tile 64, 2-stage cp.async, 128 threads
#define KT 64
#define A_STAGE_BYTES (64*128)
#define B_STAGE_BYTES (64*256)
#define STAGE_BYTES (A_STAGE_BYTES + B_STAGE_BYTES)   // 24576
#define NSTAGE 2
#define GEMM_SMEM (NSTAGE*STAGE_BYTES)                // 49152

// Scratch
__device__ __align__(16) __nv_bfloat16 g_xh[NTOT];
__device__ __align__(16) __nv_bfloat16 g_pad[BB*CC*PADP];
__device__ __align__(16) __nv_bfloat16 g_toph[NTOT];
__device__ __align__(16) __nv_bfloat16 g_out2h[NTOT];
__device__ __align__(16) __nv_bfloat16 g_w1h[CC*CC];
__device__ __align__(16) __nv_bfloat16 g_w2h[CC*CC];
__device__ float g_sum[BB*CC];
__device__ float g_se[BB*CC];

// ---------------------------------------------------------------------------
__device__ __forceinline__ uint32_t s2u(const void* p) {
    uint32_t a;
    asm("{ .reg .u64 t; cvta.to.shared.u64 t, %1; cvt.u32.u64 %0, t; }"
        : "=r"(a) : "l"(p));
    return a;
}
__device__ __forceinline__ void cpa16(uint32_t dst, const void* src, bool pred) {
    asm volatile("cp.async.cg.shared.global [%0], [%1], 16, %2;"
                 :: "r"(dst), "l"(src), "r"(pred ? 16u : 0u));
}
#define CPA_COMMIT() asm volatile("cp.async.commit_group;" ::: "memory")

__device__ __forceinline__ void ldsm4(uint32_t& r0, uint32_t& r1, uint32_t& r2,
                                      uint32_t& r3, uint32_t addr) {
    asm volatile("ldmatrix.sync.aligned.m8n8.x4.shared.b16 {%0,%1,%2,%3}, [%4];"
                 : "=r"(r0), "=r"(r1), "=r"(r2), "=r"(r3) : "r"(addr));
}
__device__ __forceinline__ void ldsm4t(uint32_t& r0, uint32_t& r1, uint32_t& r2,
                                       uint32_t& r3, uint32_t addr) {
    asm volatile("ldmatrix.sync.aligned.m8n8.x4.trans.shared.b16 {%0,%1,%2,%3}, [%4];"
                 : "=r"(r0), "=r"(r1), "=r"(r2), "=r"(r3) : "r"(addr));
}
__device__ __forceinline__ void mma_bf16(float c[4], const uint32_t a[4],
                                         const uint32_t b[2]) {
    asm volatile(
        "mma.sync.aligned.m16n8k16.row.col.f32.bf16.bf16.f32 "
        "{%0,%1,%2,%3}, {%4,%5,%6,%7}, {%8,%9}, {%0,%1,%2,%3};"
        : "+f"(c[0]), "+f"(c[1]), "+f"(c[2]), "+f"(c[3])
        : "r"(a[0]), "r"(a[1]), "r"(a[2]), "r"(a[3]), "r"(b[0]), "r"(b[1]));
}

// ---------------------------------------------------------------------------
// GEMM mainloop (R10 proven config): C[64 x 128] = A[64 x 256] * B[256 x 128]
__device__ __forceinline__ void gemm_main(const __nv_bfloat16* __restrict__ Ag,
                                          const __nv_bfloat16* __restrict__ Bg,
                                          int nvalid, float c[2][8][4]) {
    extern __shared__ char sm[];
    const int tid  = threadIdx.x;
    const int lane = tid & 31;
    const int w    = tid >> 5;
    const int wm   = w >> 1, wn = w & 1;
    const uint32_t sbase = s2u(sm);

    const int rowl = (lane & 7) + ((lane >> 3) & 1) * 8;
    const int hi   = lane >> 4;
    const int xr   = rowl & 7;

    #pragma unroll
    for (int i = 0; i < 2; i++)
        #pragma unroll
        for (int j = 0; j < 8; j++)
            #pragma unroll
            for (int r = 0; r < 4; r++) c[i][j][r] = 0.f;

    auto load_stage = [&](int t) {
        const int kt = t * KT;
        const uint32_t abase = sbase + (uint32_t)(t & 1) * STAGE_BYTES;
        const uint32_t bbase = abase + A_STAGE_BYTES;
        #pragma unroll
        for (int it = 0; it < 4; it++) {
            int q  = tid + it * 128;
            int m  = q >> 3, ch = q & 7;
            cpa16(abase + m*128 + ((ch ^ (m & 7)) << 4),
                  Ag + (size_t)m * 256 + kt + ch * 8, true);
        }
        #pragma unroll
        for (int it = 0; it < 8; it++) {
            int q  = tid + it * 128;
            int k  = q >> 4, ch = q & 15;
            cpa16(bbase + k*256 + ((ch ^ (k & 7)) << 4),
                  Bg + (size_t)(kt + k) * PP + ch * 8, ch * 8 < nvalid);
        }
        CPA_COMMIT();
    };

    load_stage(0); load_stage(1);

    const uint32_t a_off = (uint32_t)((wm*32 + rowl) * 128);
    const uint32_t b_off = (uint32_t)(A_STAGE_BYTES + rowl * 256);

    #pragma unroll 1
    for (int t = 0; t < 4; t++) {
        asm volatile("cp.async.wait_group 1;" ::: "memory");
        __syncthreads();

        const uint32_t st = sbase + (uint32_t)(t & 1) * STAGE_BYTES;
        #pragma unroll
        for (int kk2 = 0; kk2 < 4; kk2++) {
            uint32_t a[2][4], bf[8][2];
            #pragma unroll
            for (int i = 0; i < 2; i++)
                ldsm4(a[i][0], a[i][1], a[i][2], a[i][3],
                      st + a_off + i*16*128 + (((kk2*2 + hi) ^ xr) << 4));
            #pragma unroll
            for (int j2 = 0; j2 < 4; j2++)
                ldsm4t(bf[j2*2][0], bf[j2*2][1], bf[j2*2+1][0], bf[j2*2+1][1],
                       st + b_off + kk2*16*256 + (((wn*8 + j2*2 + hi) ^ xr) << 4));
            #pragma unroll
            for (int i = 0; i < 2; i++)
                #pragma unroll
                for (int j = 0; j < 8; j++)
                    mma_bf16(c[i][j], a[i], bf[j]);
        }
        __syncthreads();
        if (t + 2 < 4) load_stage(t + 2);
        else           CPA_COMMIT();
    }
}

// ---------------------------------------------------------------------------
// K1: pw1 GEMM -> g_pad
__global__ __launch_bounds__(128, 4) void k_pw1() {
    cudaGridDependencySynchronize();   // wait k_pre (weights + x bf16)
    const int b  = blockIdx.z;
    const int o0 = blockIdx.y * 64;
    const int p0 = blockIdx.x * 128;
    const int lane = threadIdx.x & 31, w = threadIdx.x >> 5;
    const int wm = w >> 1, wn = w & 1;

    float c[2][8][4];
    gemm_main(g_w1h + (size_t)o0 * 256, g_xh + (size_t)b * CC * PP + p0, PP - p0, c);

    __nv_bfloat16* dst = g_pad + (size_t)(b * CC) * PADP;
    #pragma unroll
    for (int i = 0; i < 2; i++) {
        int o = o0 + wm*32 + i*16 + (lane >> 2);
        #pragma unroll
        for (int j = 0; j < 8; j++) {
            int p = p0 + wn*64 + j*8 + (lane & 3)*2;
            if (p < PP) {
                int h = p / WW, ww = p - h * WW;
                int off = (h + 2) * 64 + ww + 2;
                *reinterpret_cast<__nv_bfloat162*>(dst + (size_t)o * PADP + off) =
                    __floats2bfloat162_rn(c[i][j][0], c[i][j][1]);
                *reinterpret_cast<__nv_bfloat162*>(dst + (size_t)(o+8) * PADP + off) =
                    __floats2bfloat162_rn(c[i][j][2], c[i][j][3]);
            }
        }
    }
    cudaTriggerProgrammaticLaunchCompletion();
}

// ---------------------------------------------------------------------------
// K3: pw2 GEMM + BN + ReLU + SE squeeze -> g_out2h, g_sum
__global__ __launch_bounds__(128, 4) void k_pw2(
    const float* __restrict__ bn2_g, const float* __restrict__ bn2_b,
    const float* __restrict__ bn2_m, const float* __restrict__ bn2_v) {
    cudaGridDependencySynchronize();   // wait k_dw (g_toph)
    const int b  = blockIdx.z;
    const int o0 = blockIdx.y * 64;
    const int p0 = blockIdx.x * 128;
    const int lane = threadIdx.x & 31, w = threadIdx.x >> 5;
    const int wm = w >> 1, wn = w & 1;

    float c[2][8][4];
    gemm_main(g_w2h + (size_t)o0 * 256, g_toph + (size_t)b * CC * PP + p0, PP - p0, c);

    __nv_bfloat16* dst = g_out2h + (size_t)b * CC * PP;
    #pragma unroll
    for (int i = 0; i < 2; i++) {
        int o = o0 + wm*32 + i*16 + (lane >> 2);
        float sc0 = bn2_g[o]   * rsqrtf(bn2_v[o]   + EPSF);
        float sh0 = bn2_b[o]   - bn2_m[o]   * sc0;
        float sc1 = bn2_g[o+8] * rsqrtf(bn2_v[o+8] + EPSF);
        float sh1 = bn2_b[o+8] - bn2_m[o+8] * sc1;
        float s0 = 0.f, s1 = 0.f;
        #pragma unroll
        for (int j = 0; j < 8; j++) {
            int pn = wn*64 + j*8 + (lane & 3)*2;
            if (p0 + pn < PP) {
                float v0 = fmaxf(fmaf(c[i][j][0], sc0, sh0), 0.f);
                float v1 = fmaxf(fmaf(c[i][j][1], sc0, sh0), 0.f);
                float v2 = fmaxf(fmaf(c[i][j][2], sc1, sh1), 0.f);
                float v3 = fmaxf(fmaf(c[i][j][3], sc1, sh1), 0.f);
                *reinterpret_cast<__nv_bfloat162*>(dst + (size_t)o * PP + p0 + pn) =
                    __floats2bfloat162_rn(v0, v1);
                *reinterpret_cast<__nv_bfloat162*>(dst + (size_t)(o+8) * PP + p0 + pn) =
                    __floats2bfloat162_rn(v2, v3);
                s0 += v0 + v1;
                s1 += v2 + v3;
            }
        }
        s0 += __shfl_xor_sync(0xFFFFFFFF, s0, 1);
        s0 += __shfl_xor_sync(0xFFFFFFFF, s0, 2);
        s1 += __shfl_xor_sync(0xFFFFFFFF, s1, 1);
        s1 += __shfl_xor_sync(0xFFFFFFFF, s1, 2);
        if ((lane & 3) == 0) {
            atomicAdd(&g_sum[b*CC + o],     s0);
            atomicAdd(&g_sum[b*CC + o + 8], s1);
        }
    }
    cudaTriggerProgrammaticLaunchCompletion();
}

// ---------------------------------------------------------------------------
// K0 (merged prep): x->bf16 convert, weight convert, SE zero, pad-border zero.
__global__ __launch_bounds__(256) void k_pre(const float* __restrict__ X,
                                             const float* __restrict__ W1,
                                             const float* __restrict__ W2) {
    const int bid = blockIdx.x;
    const int tid = threadIdx.x;

    size_t i = ((size_t)bid * 256 + tid) * 8;
    if (i < NTOT) {
        float4 a = *reinterpret_cast<const float4*>(X + i);
        float4 b = *reinterpret_cast<const float4*>(X + i + 4);
        __nv_bfloat162 o[4];
        o[0] = __floats2bfloat162_rn(a.x, a.y);
        o[1] = __floats2bfloat162_rn(a.z, a.w);
        o[2] = __floats2bfloat162_rn(b.x, b.y);
        o[3] = __floats2bfloat162_rn(b.z, b.w);
        *reinterpret_cast<uint4*>(g_xh + i) = *reinterpret_cast<uint4*>(o);
    }
    if (bid < 256) {
        int j = bid * 256 + tid;
        g_w1h[j] = __float2bfloat16(W1[j]);
        g_w2h[j] = __float2bfloat16(W2[j]);
    }
    if (bid < 16) g_sum[bid * 256 + tid] = 0.f;
    if (bid < BB*CC) {
        __nv_bfloat16* P = g_pad + (size_t)bid * PADP;
        {
            int r = tid >> 6;
            int row = (r < 2) ? r : 56 + r;
            P[row * 64 + (tid & 63)] = __nv_bfloat16(0.f);
        }
        #pragma unroll
        for (int it = 0; it < 2; it++) {
            int q = tid + it * 256;
            if (q < 448) {
                int row = 2 + (q >> 3);
                int ci = q & 7;
                int col = (ci < 2) ? ci : ci + 56;
                P[row * 64 + col] = __nv_bfloat16(0.f);
            }
        }
    }
    cudaTriggerProgrammaticLaunchCompletion();
}

// ---------------------------------------------------------------------------
// K2: fused depthwise + BN + ReLU + gate. Independent prologue hoisted
// before grid-dependency sync (PDL overlap with pw1's tail).
__global__ __launch_bounds__(256) void k_dw(
    const float* __restrict__ xy3, const float* __restrict__ xy5,
    const float* __restrict__ bnxy_g, const float* __restrict__ bnxy_b,
    const float* __restrict__ bnxy_m, const float* __restrict__ bnxy_v,
    const float* __restrict__ xz3, const float* __restrict__ xz5,
    const float* __restrict__ bnxz_g, const float* __restrict__ bnxz_b,
    const float* __restrict__ bnxz_m, const float* __restrict__ bnxz_v,
    const float* __restrict__ yz3, const float* __restrict__ yz5,
    const float* __restrict__ bnyz_g, const float* __restrict__ bnyz_b,
    const float* __restrict__ bnyz_m, const float* __restrict__ bnyz_v,
    const float* __restrict__ alpha, const float* __restrict__ beta) {

    const int c = blockIdx.x;
    const int b = blockIdx.y;
    const int tid = threadIdx.x;

    __shared__ float sp[60*SPITCH];
    __shared__ float swe[36];

    // ---- independent prologue (reads only kernel inputs) ----
    if (tid < 25) {
        int i = tid / 5, j = tid - i*5;
        float v = xy5[c*25 + tid];
        if (i >= 1 && i <= 3 && j >= 1 && j <= 3) v += xy3[c*9 + (i-1)*3 + (j-1)];
        swe[tid] = v;
    } else if (tid < 30) {
        int j = tid - 25;
        float v = xz5[c*5 + j];
        if (j >= 1 && j <= 3) v += xz3[c*3 + j - 1];
        swe[tid] = v;
    } else if (tid < 35) {
        int i = tid - 30;
        float v = yz5[c*5 + i];
        if (i >= 1 && i <= 3) v += yz3[c*3 + i - 1];
        swe[tid] = v;
    }
    const float scxy = bnxy_g[c] * rsqrtf(bnxy_v[c] + EPSF);
    const float shxy = bnxy_b[c] - bnxy_m[c] * scxy;
    const float scxz = bnxz_g[c] * rsqrtf(bnxz_v[c] + EPSF);
    const float shxz = bnxz_b[c] - bnxz_m[c] * scxz;
    const float scyz = bnyz_g[c] * rsqrtf(bnyz_v[c] + EPSF);
    const float shyz = bnyz_b[c] - bnyz_m[c] * scyz;
    const float al = alpha[c], be = beta[c];

    // ---- dependent part ----
    cudaGridDependencySynchronize();   // wait k_pw1 (g_pad)
    {
        const __nv_bfloat16* src = g_pad + (size_t)(b*CC + c) * PADP;
        #pragma unroll
        for (int it = 0; it < 2; it++) {
            int idx = tid + it * 256;
            if (idx < 480) {
                int row = idx >> 3, col = (idx & 7) * 8;
                uint4 raw = *reinterpret_cast<const uint4*>(src + row*64 + col);
                const __nv_bfloat162* h2 = reinterpret_cast<const __nv_bfloat162*>(&raw);
                float* d = sp + row*SPITCH + col;
                #pragma unroll
                for (int q = 0; q < 4; q++) {
                    float2 f = __bfloat1622float2(h2[q]);
                    d[q*2]   = f.x;
                    d[q*2+1] = f.y;
                }
            }
        }
    }
    __syncthreads();

    if (tid >= 224) return;
    const int row = tid >> 2;
    const int seg = (tid & 3) * 14;

    float we[25], wxz[5], wyz[5];
    #pragma unroll
    for (int i = 0; i < 25; i++) we[i] = swe[i];
    #pragma unroll
    for (int i = 0; i < 5; i++) { wxz[i] = swe[25+i]; wyz[i] = swe[30+i]; }

    float win[5][5];
    const float* spr = sp + row*SPITCH + seg;
    #pragma unroll
    for (int i = 0; i < 5; i++)
        #pragma unroll
        for (int j = 0; j < 5; j++)
            win[i][j] = spr[i*SPITCH + j];

    __nv_bfloat162 outbuf[7];
    #pragma unroll
    for (int s = 0; s < 14; s++) {
        float sxy = 0.f, sxz = 0.f, syz = 0.f;
        #pragma unroll
        for (int i = 0; i < 5; i++)
            #pragma unroll
            for (int j = 0; j < 5; j++)
                sxy = fmaf(win[i][(s+j) % 5], we[i*5+j], sxy);
        #pragma unroll
        for (int j = 0; j < 5; j++) sxz = fmaf(win[2][(s+j) % 5], wxz[j], sxz);
        #pragma unroll
        for (int i = 0; i < 5; i++) syz = fmaf(win[i][(s+2) % 5], wyz[i], syz);

        float fxy = fmaxf(fmaf(sxy, scxy, shxy), 0.f);
        float fxz = fmaxf(fmaf(sxz, scxz, shxz), 0.f);
        float fyz = fmaxf(fmaf(syz, scyz, shyz), 0.f);
        float z = fmaf(al, fxz, be * fyz);
        float gate = __fdividef(1.f, 1.f + __expf(-z));
        float r = fmaxf(fxy * gate, 0.f);
        __nv_bfloat16 h = __float2bfloat16(r);
        if (s & 1) outbuf[s >> 1].y = h;
        else       outbuf[s >> 1].x = h;

        if (s < 13) {
            #pragma unroll
            for (int i = 0; i < 5; i++)
                win[i][s % 5] = spr[i*SPITCH + s + 5];
        }
    }
    __nv_bfloat16* dst = g_toph + (size_t)(b*CC + c) * PP + row*WW + seg;
    #pragma unroll
    for (int s = 0; s < 7; s++)
        *reinterpret_cast<__nv_bfloat162*>(dst + 2*s) = outbuf[s];
    cudaTriggerProgrammaticLaunchCompletion();
}

// ---------------------------------------------------------------------------
// K4: SE MLP per batch
__global__ __launch_bounds__(256) void k_se(
    const float* __restrict__ fc1_w, const float* __restrict__ fc1_b,
    const float* __restrict__ fc2_w, const float* __restrict__ fc2_b) {
    cudaGridDependencySynchronize();   // wait k_pw2 (g_sum)
    const int b = blockIdx.x;
    const int tid = threadIdx.x;
    __shared__ float s[CC];
    __shared__ float t[16];
    s[tid] = g_sum[b*CC + tid] * (1.f / (float)PP);
    __syncthreads();
    if (tid < 16) {
        float acc = fc1_b[tid];
        #pragma unroll 8
        for (int c = 0; c < CC; c++) acc = fmaf(fc1_w[tid*CC + c], s[c], acc);
        t[tid] = fmaxf(acc, 0.f);
    }
    __syncthreads();
    float acc = fc2_b[tid];
    #pragma unroll
    for (int m = 0; m < 16; m++) acc = fmaf(fc2_w[tid*16 + m], t[m], acc);
    g_se[b*CC + tid] = __fdividef(1.f, 1.f + __expf(-acc));
    cudaTriggerProgrammaticLaunchCompletion();
}

// ---------------------------------------------------------------------------
// K5: out = out2(bf16) * se[b,c] + x   (8 elems/thread)
__global__ __launch_bounds__(256) void k_final(const float* __restrict__ X,
                                               float* __restrict__ O) {
    cudaGridDependencySynchronize();   // wait k_se (g_se)
    size_t i = ((size_t)blockIdx.x * 256 + threadIdx.x) * 8;
    if (i >= NTOT) return;
    int bc = (int)(i / PP);
    float sf = g_se[bc];
    uint4 raw = *reinterpret_cast<const uint4*>(g_out2h + i);
    const __nv_bfloat162* h2 = reinterpret_cast<const __nv_bfloat162*>(&raw);
    float4 x0 = *reinterpret_cast<const float4*>(X + i);
    float4 x1 = *reinterpret_cast<const float4*>(X + i + 4);
    float2 f0 = __bfloat1622float2(h2[0]);
    float2 f1 = __bfloat1622float2(h2[1]);
    float2 f2 = __bfloat1622float2(h2[2]);
    float2 f3 = __bfloat1622float2(h2[3]);
    float4 r0, r1;
    r0.x = fmaf(f0.x, sf, x0.x); r0.y = fmaf(f0.y, sf, x0.y);
    r0.z = fmaf(f1.x, sf, x0.z); r0.w = fmaf(f1.y, sf, x0.w);
    r1.x = fmaf(f2.x, sf, x1.x); r1.y = fmaf(f2.y, sf, x1.y);
    r1.z = fmaf(f3.x, sf, x1.z); r1.w = fmaf(f3.y, sf, x1.w);
    *reinterpret_cast<float4*>(O + i)     = r0;
    *reinterpret_cast<float4*>(O + i + 4) = r1;
}

// ---------------------------------------------------------------------------
template <typename... Args>
static void pdl_launch(void (*kern)(Args...), dim3 grid, dim3 block,
                       size_t smem, bool pdl, Args... args) {
    cudaLaunchConfig_t cfg = {};
    cfg.gridDim = grid;
    cfg.blockDim = block;
    cfg.dynamicSmemBytes = smem;
    cfg.stream = 0;
    cudaLaunchAttribute attr[1];
    attr[0].id = cudaLaunchAttributeProgrammaticStreamSerialization;
    attr[0].val.programmaticStreamSerializationAllowed = 1;
    cfg.attrs = attr;
    cfg.numAttrs = pdl ? 1 : 0;
    cudaLaunchKernelEx(&cfg, kern, args...);
}

extern "C" void kernel_launch(void* const* d_in, const int* in_sizes, int n_in,
                              void* d_out, int out_size) {
    const float* x      = (const float*)d_in[0];
    const float* pw1_w  = (const float*)d_in[1];
    const float* xy3_w  = (const float*)d_in[2];
    const float* xy5_w  = (const float*)d_in[3];
    const float* bnxy_g = (const float*)d_in[4];
    const float* bnxy_b = (const float*)d_in[5];
    const float* bnxy_m = (const float*)d_in[6];
    const float* bnxy_v = (const float*)d_in[7];
    const float* xz3_w  = (const float*)d_in[8];
    const float* xz5_w  = (const float*)d_in[9];
    const float* bnxz_g = (const float*)d_in[10];
    const float* bnxz_b = (const float*)d_in[11];
    const float* bnxz_m = (const float*)d_in[12];
    const float* bnxz_v = (const float*)d_in[13];
    const float* yz3_w  = (const float*)d_in[14];
    const float* yz5_w  = (const float*)d_in[15];
    const float* bnyz_g = (const float*)d_in[16];
    const float* bnyz_b = (const float*)d_in[17];
    const float* bnyz_m = (const float*)d_in[18];
    const float* bnyz_v = (const float*)d_in[19];
    const float* alpha  = (const float*)d_in[20];
    const float* beta   = (const float*)d_in[21];
    const float* pw2_w  = (const float*)d_in[22];
    const float* bn2_g  = (const float*)d_in[23];
    const float* bn2_b  = (const float*)d_in[24];
    const float* bn2_m  = (const float*)d_in[25];
    const float* bn2_v  = (const float*)d_in[26];
    const float* fc1_w  = (const float*)d_in[27];
    const float* fc1_b  = (const float*)d_in[28];
    const float* fc2_w  = (const float*)d_in[29];
    const float* fc2_b  = (const float*)d_in[30];
    float* out = (float*)d_out;

    static bool attr_done = false;
    if (!attr_done) {
        cudaFuncSetAttribute(k_pw1, cudaFuncAttributeMaxDynamicSharedMemorySize, GEMM_SMEM);
        cudaFuncSetAttribute(k_pw2, cudaFuncAttributeMaxDynamicSharedMemorySize, GEMM_SMEM);
        attr_done = true;
    }

    pdl_launch(k_pre, dim3((NTOT/8 + 255)/256), dim3(256), 0, false, x, pw1_w, pw2_w);
    pdl_launch(k_pw1, dim3(25, 4, BB), dim3(128), (size_t)GEMM_SMEM, true);
    pdl_launch(k_dw, dim3(CC, BB), dim3(256), 0, true,
               xy3_w, xy5_w, bnxy_g, bnxy_b, bnxy_m, bnxy_v,
               xz3_w, xz5_w, bnxz_g, bnxz_b, bnxz_m, bnxz_v,
               yz3_w, yz5_w, bnyz_g, bnyz_b, bnyz_m, bnyz_v,
               alpha, beta);
    pdl_launch(k_pw2, dim3(25, 4, BB), dim3(128), (size_t)GEMM_SMEM, true,
               bn2_g, bn2_b, bn2_m, bn2_v);
    pdl_launch(k_se, dim3(BB), dim3(256), 0, true, fc1_w, fc1_b, fc2_w, fc2_b);
    pdl_launch(k_final, dim3((NTOT/8 + 255)/256), dim3(256), 0, true, x, out);
}